// round 1
// baseline (speedup 1.0000x reference)
#include <cuda_runtime.h>
#include <cuda_bf16.h>
#include <cstdint>

// Problem constants (shapes are fixed by the dataset, but sizes are re-derived
// from in_sizes at launch for safety).
#define DIN 512
#define DOUT 64
#define NEG_SLOPE 0.2f

// Scratch: support = leaky_relu(features @ W), N x 64 fp32 = 25.6 MB.
// __device__ global (no allocation allowed in kernel_launch).
#define N_MAX 100000
__device__ float g_support[(size_t)N_MAX * DOUT];

// ---------------------------------------------------------------------------
// Phase 1: C[n,64] = leaky_relu(A[n,512] @ W[512,64])
// Classic shared-memory tiled fp32 GEMM. BM=64, BN=64, BK=16, 256 threads,
// 4x4 register micro-tile per thread.
// ---------------------------------------------------------------------------
__global__ __launch_bounds__(256) void gemm_leaky_kernel(
    const float* __restrict__ A, const float* __restrict__ W,
    float* __restrict__ C, int n)
{
    __shared__ float As[16][64 + 1];  // [k][m], padded to dodge bank conflicts
    __shared__ float Ws[16][64 + 1];  // [k][c]

    const int tid = threadIdx.x;
    const int tx = tid & 15;          // column group 0..15
    const int ty = tid >> 4;          // row group    0..15
    const int row0 = blockIdx.x * 64;

    // A-tile load mapping: thread -> (m, 4-wide k chunk)
    const int a_m  = tid >> 2;        // 0..63
    const int a_k4 = (tid & 3) << 2;  // 0,4,8,12
    const int a_row = row0 + a_m;
    const bool a_ok = (a_row < n);

    // W-tile load mapping: thread -> 4 consecutive floats of the 16x64 tile
    const int w_lin = tid << 2;       // 0..1020
    const int w_k = w_lin >> 6;       // 0..15
    const int w_c = w_lin & 63;

    float acc[4][4] = {};

    for (int k0 = 0; k0 < DIN; k0 += 16) {
        // Load A 64x16 tile (transposed into As[k][m])
        float4 a4;
        if (a_ok) {
            a4 = *reinterpret_cast<const float4*>(A + (size_t)a_row * DIN + k0 + a_k4);
        } else {
            a4 = make_float4(0.f, 0.f, 0.f, 0.f);
        }
        As[a_k4 + 0][a_m] = a4.x;
        As[a_k4 + 1][a_m] = a4.y;
        As[a_k4 + 2][a_m] = a4.z;
        As[a_k4 + 3][a_m] = a4.w;

        // Load W 16x64 tile
        float4 w4 = *reinterpret_cast<const float4*>(W + (size_t)(k0 + w_k) * DOUT + w_c);
        Ws[w_k][w_c + 0] = w4.x;
        Ws[w_k][w_c + 1] = w4.y;
        Ws[w_k][w_c + 2] = w4.z;
        Ws[w_k][w_c + 3] = w4.w;

        __syncthreads();

        #pragma unroll
        for (int kk = 0; kk < 16; kk++) {
            float a[4], b[4];
            #pragma unroll
            for (int i = 0; i < 4; i++) a[i] = As[kk][ty * 4 + i];
            #pragma unroll
            for (int j = 0; j < 4; j++) b[j] = Ws[kk][tx * 4 + j];
            #pragma unroll
            for (int i = 0; i < 4; i++)
                #pragma unroll
                for (int j = 0; j < 4; j++)
                    acc[i][j] = fmaf(a[i], b[j], acc[i][j]);
        }
        __syncthreads();
    }

    // Epilogue: LeakyReLU(0.2) + store
    #pragma unroll
    for (int i = 0; i < 4; i++) {
        int r = row0 + ty * 4 + i;
        if (r < n) {
            #pragma unroll
            for (int j = 0; j < 4; j++) {
                float v = acc[i][j];
                v = (v > 0.f) ? v : NEG_SLOPE * v;
                C[(size_t)r * DOUT + tx * 4 + j] = v;
            }
        }
    }
}

// ---------------------------------------------------------------------------
// Phase 2/3: out[r] += val[e] * x[col[e]]  (COO SpMM, DOUT=64)
// 16 threads per edge, one float4 column chunk each.
// Scatter via red.global.add.v4.f32 (sm_90+): 16B L2-resident reductions.
// ---------------------------------------------------------------------------
__global__ __launch_bounds__(256) void spmm_red_kernel(
    const int* __restrict__ rows, const int* __restrict__ cols,
    const float* __restrict__ vals, const float* __restrict__ x,
    float* __restrict__ out, int E)
{
    const long long idx = (long long)blockIdx.x * blockDim.x + threadIdx.x;
    const long long e = idx >> 4;
    if (e >= E) return;
    const int c = (int)(idx & 15);

    const int   r  = __ldg(rows + e);
    const int   co = __ldg(cols + e);
    const float v  = __ldg(vals + e);

    const float4 s = *reinterpret_cast<const float4*>(x + ((size_t)co << 6) + (c << 2));
    const float4 o = make_float4(s.x * v, s.y * v, s.z * v, s.w * v);

    float* p = out + ((size_t)r << 6) + (c << 2);
    asm volatile("red.global.add.v4.f32 [%0], {%1, %2, %3, %4};"
                 :: "l"(p), "f"(o.x), "f"(o.y), "f"(o.z), "f"(o.w)
                 : "memory");
}

// ---------------------------------------------------------------------------
// kernel_launch
// Inputs (metadata order): features [N*512 f32], weight [512*64 f32],
//   edge_rows [E i32], edge_cols [E i32], edge_vals [E f32]
// Output: concat(output [N*64 f32], az [N*64 f32])
// ---------------------------------------------------------------------------
extern "C" void kernel_launch(void* const* d_in, const int* in_sizes, int n_in,
                              void* d_out, int out_size)
{
    const float* features = (const float*)d_in[0];
    const float* weight   = (const float*)d_in[1];
    const int*   erows    = (const int*)d_in[2];
    const int*   ecols    = (const int*)d_in[3];
    const float* evals    = (const float*)d_in[4];
    float* out = (float*)d_out;

    const int n = in_sizes[0] / DIN;     // 100000
    const int E = in_sizes[2];           // 1600000

    float* out_output = out;                       // first  N*64
    float* out_az     = out + (size_t)n * DOUT;    // second N*64

    float* support = nullptr;
    cudaGetSymbolAddress((void**)&support, g_support);

    // Zero both output halves (poisoned to 0xAA by harness; reductions need 0)
    cudaMemsetAsync(d_out, 0, (size_t)out_size * sizeof(float));

    // Phase 1: support = leaky_relu(features @ weight)
    gemm_leaky_kernel<<<(n + 63) / 64, 256>>>(features, weight, support, n);

    // Phase 2: output = adj @ support
    {
        long long work = (long long)E * 16;
        int grid = (int)((work + 255) / 256);
        spmm_red_kernel<<<grid, 256>>>(erows, ecols, evals, support, out_output, E);
    }

    // Phase 3: az = adj @ output
    {
        long long work = (long long)E * 16;
        int grid = (int)((work + 255) / 256);
        spmm_red_kernel<<<grid, 256>>>(erows, ecols, evals, out_output, out_az, E);
    }
}

// round 3
// speedup vs baseline: 1.2978x; 1.2978x over previous
#include <cuda_runtime.h>
#include <cuda_bf16.h>
#include <cstdint>

#define DIN 512
#define DOUT 64
#define NEG_SLOPE 0.2f
#define N_MAX 100000

// Scratch (no allocation allowed): support = leaky(A@W), and tf32-split weight.
__device__ float g_support[(size_t)N_MAX * DOUT];
__device__ float g_Bhi[DIN * DOUT];
__device__ float g_Blo[DIN * DOUT];

// ---------------------------------------------------------------------------
// Prep: split W into tf32-exact hi (mantissa-truncated) + fp32 residual lo.
// ---------------------------------------------------------------------------
__global__ void split_w_kernel(const float* __restrict__ W,
                               float* __restrict__ bhi, float* __restrict__ blo,
                               int total)
{
    int i = blockIdx.x * blockDim.x + threadIdx.x;
    if (i < total) {
        float w = W[i];
        unsigned h = __float_as_uint(w) & 0xffffe000u;
        float hf = __uint_as_float(h);
        bhi[i] = hf;
        blo[i] = w - hf;
    }
}

// ---------------------------------------------------------------------------
// GEMM via 3xTF32 mma.sync: C[n,64] = leaky_relu(A[n,512] @ W[512,64])
// BM=128, BK=32, 256 threads = 8 warps; warp w owns rows [w*16, w*16+16),
// all 64 cols as 8 n-tiles of m16n8k8.
// smem strides chosen for conflict-free LDS of mma fragments:
//   A stride 36: bank = (4g + t)  -> all 32 lanes distinct
//   B stride 72: bank = (8t + g)  -> all 32 lanes distinct
// ---------------------------------------------------------------------------
#define BM 128
#define BK 32

__device__ __forceinline__ void mma_tf32(float c[4],
                                         unsigned a0, unsigned a1, unsigned a2, unsigned a3,
                                         unsigned b0, unsigned b1)
{
    asm volatile(
        "mma.sync.aligned.m16n8k8.row.col.f32.tf32.tf32.f32 "
        "{%0,%1,%2,%3}, {%4,%5,%6,%7}, {%8,%9}, {%0,%1,%2,%3};"
        : "+f"(c[0]), "+f"(c[1]), "+f"(c[2]), "+f"(c[3])
        : "r"(a0), "r"(a1), "r"(a2), "r"(a3), "r"(b0), "r"(b1));
}

__global__ __launch_bounds__(256) void gemm_tf32_kernel(
    const float* __restrict__ A,
    const float* __restrict__ Bhi, const float* __restrict__ Blo,
    float* __restrict__ C, int n)
{
    __shared__ float As[BM][36];     // [row][k] of current K-chunk
    __shared__ float Bh[BK][72];     // [k][n]
    __shared__ float Bl[BK][72];

    const int tid  = threadIdx.x;
    const int warp = tid >> 5;
    const int lane = tid & 31;
    const int g = lane >> 2;         // 0..7
    const int t = lane & 3;          // 0..3
    const int row0 = blockIdx.x * BM;

    // A-tile load mapping: 128x32 floats = 1024 float4, 4 per thread
    const int am = tid >> 3;          // 0..31
    const int ak = (tid & 7) << 2;    // 0..28

    float c[8][4];
    #pragma unroll
    for (int j = 0; j < 8; j++)
        #pragma unroll
        for (int q = 0; q < 4; q++) c[j][q] = 0.f;

    for (int k0 = 0; k0 < DIN; k0 += BK) {
        // --- load A chunk (coalesced float4) ---
        #pragma unroll
        for (int p = 0; p < 4; p++) {
            int rl = am + p * 32;              // local row 0..127
            int r  = row0 + rl;
            float4 v = make_float4(0.f, 0.f, 0.f, 0.f);
            if (r < n)
                v = *reinterpret_cast<const float4*>(A + (size_t)r * DIN + k0 + ak);
            As[rl][ak + 0] = v.x; As[rl][ak + 1] = v.y;
            As[rl][ak + 2] = v.z; As[rl][ak + 3] = v.w;
        }
        // --- load B chunk (hi + lo), 32x64 floats = 512 float4, 2 per thread ---
        #pragma unroll
        for (int q = 0; q < 2; q++) {
            int idx = tid * 2 + q;
            int bk = idx >> 4;                 // 0..31
            int bn = (idx & 15) << 2;          // 0..60
            const float4 vh = *reinterpret_cast<const float4*>(Bhi + (size_t)(k0 + bk) * DOUT + bn);
            const float4 vl = *reinterpret_cast<const float4*>(Blo + (size_t)(k0 + bk) * DOUT + bn);
            Bh[bk][bn + 0] = vh.x; Bh[bk][bn + 1] = vh.y;
            Bh[bk][bn + 2] = vh.z; Bh[bk][bn + 3] = vh.w;
            Bl[bk][bn + 0] = vl.x; Bl[bk][bn + 1] = vl.y;
            Bl[bk][bn + 2] = vl.z; Bl[bk][bn + 3] = vl.w;
        }
        __syncthreads();

        #pragma unroll
        for (int kk = 0; kk < BK / 8; kk++) {
            const int kc = kk * 8;
            // A fragments (m16k8, row-major) for this warp
            const float a0f = As[warp * 16 + g    ][kc + t    ];
            const float a1f = As[warp * 16 + g + 8][kc + t    ];
            const float a2f = As[warp * 16 + g    ][kc + t + 4];
            const float a3f = As[warp * 16 + g + 8][kc + t + 4];
            // split: hi = exact tf32 truncation, lo = residual
            const unsigned ah0 = __float_as_uint(a0f) & 0xffffe000u;
            const unsigned ah1 = __float_as_uint(a1f) & 0xffffe000u;
            const unsigned ah2 = __float_as_uint(a2f) & 0xffffe000u;
            const unsigned ah3 = __float_as_uint(a3f) & 0xffffe000u;
            const unsigned al0 = __float_as_uint(a0f - __uint_as_float(ah0));
            const unsigned al1 = __float_as_uint(a1f - __uint_as_float(ah1));
            const unsigned al2 = __float_as_uint(a2f - __uint_as_float(ah2));
            const unsigned al3 = __float_as_uint(a3f - __uint_as_float(ah3));

            #pragma unroll
            for (int j = 0; j < 8; j++) {
                const unsigned bh0 = __float_as_uint(Bh[kc + t    ][j * 8 + g]);
                const unsigned bh1 = __float_as_uint(Bh[kc + t + 4][j * 8 + g]);
                const unsigned bl0 = __float_as_uint(Bl[kc + t    ][j * 8 + g]);
                const unsigned bl1 = __float_as_uint(Bl[kc + t + 4][j * 8 + g]);
                mma_tf32(c[j], ah0, ah1, ah2, ah3, bh0, bh1);   // hi*hi
                mma_tf32(c[j], al0, al1, al2, al3, bh0, bh1);   // lo*hi
                mma_tf32(c[j], ah0, ah1, ah2, ah3, bl0, bl1);   // hi*lo
            }
        }
        __syncthreads();
    }

    // Epilogue: LeakyReLU + store.
    const int rA = row0 + warp * 16 + g;
    const int rB = rA + 8;
    const bool okA = rA < n, okB = rB < n;
    #pragma unroll
    for (int j = 0; j < 8; j++) {
        const int col = j * 8 + 2 * t;
        if (okA) {
            float v0 = c[j][0]; v0 = (v0 > 0.f) ? v0 : NEG_SLOPE * v0;
            float v1 = c[j][1]; v1 = (v1 > 0.f) ? v1 : NEG_SLOPE * v1;
            C[(size_t)rA * DOUT + col]     = v0;
            C[(size_t)rA * DOUT + col + 1] = v1;
        }
        if (okB) {
            float v2 = c[j][2]; v2 = (v2 > 0.f) ? v2 : NEG_SLOPE * v2;
            float v3 = c[j][3]; v3 = (v3 > 0.f) ? v3 : NEG_SLOPE * v3;
            C[(size_t)rB * DOUT + col]     = v2;
            C[(size_t)rB * DOUT + col + 1] = v3;
        }
    }
}

// ---------------------------------------------------------------------------
// COO SpMM with vectorized global reductions (R1-proven: ~90us each).
// ---------------------------------------------------------------------------
__global__ __launch_bounds__(256) void spmm_red_kernel(
    const int* __restrict__ rows, const int* __restrict__ cols,
    const float* __restrict__ vals, const float* __restrict__ x,
    float* __restrict__ out, int E)
{
    const long long idx = (long long)blockIdx.x * blockDim.x + threadIdx.x;
    const long long e = idx >> 4;
    if (e >= E) return;
    const int c = (int)(idx & 15);

    const int   r  = __ldg(rows + e);
    const int   co = __ldg(cols + e);
    const float v  = __ldg(vals + e);

    const float4 s = *reinterpret_cast<const float4*>(x + ((size_t)co << 6) + (c << 2));
    const float4 o = make_float4(s.x * v, s.y * v, s.z * v, s.w * v);

    float* p = out + ((size_t)r << 6) + (c << 2);
    asm volatile("red.global.add.v4.f32 [%0], {%1, %2, %3, %4};"
                 :: "l"(p), "f"(o.x), "f"(o.y), "f"(o.z), "f"(o.w)
                 : "memory");
}

// ---------------------------------------------------------------------------
extern "C" void kernel_launch(void* const* d_in, const int* in_sizes, int n_in,
                              void* d_out, int out_size)
{
    const float* features = (const float*)d_in[0];
    const float* weight   = (const float*)d_in[1];
    const int*   erows    = (const int*)d_in[2];
    const int*   ecols    = (const int*)d_in[3];
    const float* evals    = (const float*)d_in[4];
    float* out = (float*)d_out;

    const int n = in_sizes[0] / DIN;
    const int E = in_sizes[2];

    float* out_output = out;
    float* out_az     = out + (size_t)n * DOUT;

    float *support = nullptr, *bhi = nullptr, *blo = nullptr;
    cudaGetSymbolAddress((void**)&support, g_support);
    cudaGetSymbolAddress((void**)&bhi, g_Bhi);
    cudaGetSymbolAddress((void**)&blo, g_Blo);

    // Zero outputs (poisoned to 0xAA; reductions accumulate into zeros)
    cudaMemsetAsync(d_out, 0, (size_t)out_size * sizeof(float));

    // Split weight into tf32 hi/lo
    {
        int total = DIN * DOUT;
        split_w_kernel<<<(total + 255) / 256, 256>>>(weight, bhi, blo, total);
    }

    // Phase 1: support = leaky_relu(features @ weight), 3xTF32 tensor-core GEMM
    gemm_tf32_kernel<<<(n + BM - 1) / BM, 256>>>(features, bhi, blo, support, n);

    // Phase 2: output = adj @ support
    {
        long long work = (long long)E * 16;
        spmm_red_kernel<<<(int)((work + 255) / 256), 256>>>(erows, ecols, evals, support, out_output, E);
    }
    // Phase 3: az = adj @ output
    {
        long long work = (long long)E * 16;
        spmm_red_kernel<<<(int)((work + 255) / 256), 256>>>(erows, ecols, evals, out_output, out_az, E);
    }
}

// round 5
// speedup vs baseline: 1.6563x; 1.2763x over previous
#include <cuda_runtime.h>
#include <cuda_bf16.h>
#include <cstdint>

#define DIN 512
#define DOUT 64
#define NEG_SLOPE 0.2f
#define N_MAX 100000
#define E_MAX 1600000

// ---------------- scratch (__device__ globals; no allocation allowed) ------
__device__ float g_support[(size_t)N_MAX * DOUT];
__device__ float g_Bhi[DIN * DOUT];
__device__ float g_Blo[DIN * DOUT];

__device__ int    g_rowptr[N_MAX + 1];
__device__ int    g_tmpoff[N_MAX];
__device__ int    g_bsums[128];
__device__ float2 g_ecf[E_MAX];        // packed {col_bits, val}, row-sorted

// ---------------------------------------------------------------------------
// W split: tf32-exact hi + fp32 residual lo
// ---------------------------------------------------------------------------
__global__ void split_w_kernel(const float* __restrict__ W,
                               float* __restrict__ bhi, float* __restrict__ blo,
                               int total)
{
    int i = blockIdx.x * blockDim.x + threadIdx.x;
    if (i < total) {
        float w = W[i];
        unsigned h = __float_as_uint(w) & 0xffffe000u;
        float hf = __uint_as_float(h);
        bhi[i] = hf;
        blo[i] = w - hf;
    }
}

// ---------------------------------------------------------------------------
// CSR build: histogram -> 2-level exclusive scan -> scatter permute
// ---------------------------------------------------------------------------
__global__ void hist_kernel(const int* __restrict__ rows, int* __restrict__ cnt, int E)
{
    int i = blockIdx.x * blockDim.x + threadIdx.x;
    if (i < E) atomicAdd(cnt + rows[i], 1);
}

#define SCAN_B 1024
__global__ __launch_bounds__(SCAN_B) void scan_blocks_kernel(
    const int* __restrict__ cnt, int* __restrict__ rowptr,
    int* __restrict__ bsums, int n)
{
    __shared__ int s[SCAN_B];
    const int tid = threadIdx.x;
    const int i = blockIdx.x * SCAN_B + tid;
    int v = (i < n) ? cnt[i] : 0;
    s[tid] = v;
    __syncthreads();
    #pragma unroll
    for (int off = 1; off < SCAN_B; off <<= 1) {
        int t = (tid >= off) ? s[tid - off] : 0;
        __syncthreads();
        s[tid] += t;
        __syncthreads();
    }
    if (i < n) rowptr[i] = s[tid] - v;          // exclusive, pre-offset
    if (tid == SCAN_B - 1) bsums[blockIdx.x] = s[tid];
}

__global__ __launch_bounds__(128) void scan_sums_kernel(int* __restrict__ bsums, int nb)
{
    __shared__ int s[128];
    const int tid = threadIdx.x;
    int v = (tid < nb) ? bsums[tid] : 0;
    s[tid] = v;
    __syncthreads();
    #pragma unroll
    for (int off = 1; off < 128; off <<= 1) {
        int t = (tid >= off) ? s[tid - off] : 0;
        __syncthreads();
        s[tid] += t;
        __syncthreads();
    }
    if (tid < nb) bsums[tid] = s[tid] - v;      // exclusive
}

__global__ void add_offsets_kernel(int* __restrict__ rowptr,
                                   const int* __restrict__ bsums, int n, int E)
{
    int i = blockIdx.x * blockDim.x + threadIdx.x;
    if (i < n) rowptr[i] += bsums[i >> 10];
    if (i == 0) rowptr[n] = E;
}

__global__ void scatter_kernel(const int* __restrict__ rows,
                               const int* __restrict__ cols,
                               const float* __restrict__ vals,
                               int* __restrict__ off,
                               float2* __restrict__ ecf, int E)
{
    int i = blockIdx.x * blockDim.x + threadIdx.x;
    if (i < E) {
        int r = rows[i];
        int p = atomicAdd(off + r, 1);
        ecf[p] = make_float2(__int_as_float(cols[i]), vals[i]);
    }
}

// ---------------------------------------------------------------------------
// CSR SpMM: out[r,:] = sum_e val[e] * x[col[e],:].  16 threads/row, float4
// per thread, zero atomics, edge {col,val} as one 8B broadcast load.
// ---------------------------------------------------------------------------
__global__ __launch_bounds__(256) void spmm_csr_kernel(
    const int* __restrict__ rowptr, const float2* __restrict__ ecf,
    const float* __restrict__ x, float* __restrict__ out, int n)
{
    const int tid = threadIdx.x;
    const int row = blockIdx.x * 16 + (tid >> 4);
    const int c4 = (tid & 15) << 2;
    if (row >= n) return;

    const int s = __ldg(rowptr + row);
    const int e = __ldg(rowptr + row + 1);

    float4 a0 = make_float4(0.f, 0.f, 0.f, 0.f);
    float4 a1 = make_float4(0.f, 0.f, 0.f, 0.f);

    int i = s;
    for (; i + 2 <= e; i += 2) {
        const float2 cv0 = __ldg(ecf + i);
        const float2 cv1 = __ldg(ecf + i + 1);
        const int c0 = __float_as_int(cv0.x);
        const int c1 = __float_as_int(cv1.x);
        const float4 x0 = __ldg(reinterpret_cast<const float4*>(x + ((size_t)c0 << 6) + c4));
        const float4 x1 = __ldg(reinterpret_cast<const float4*>(x + ((size_t)c1 << 6) + c4));
        a0.x = fmaf(cv0.y, x0.x, a0.x); a0.y = fmaf(cv0.y, x0.y, a0.y);
        a0.z = fmaf(cv0.y, x0.z, a0.z); a0.w = fmaf(cv0.y, x0.w, a0.w);
        a1.x = fmaf(cv1.y, x1.x, a1.x); a1.y = fmaf(cv1.y, x1.y, a1.y);
        a1.z = fmaf(cv1.y, x1.z, a1.z); a1.w = fmaf(cv1.y, x1.w, a1.w);
    }
    if (i < e) {
        const float2 cv = __ldg(ecf + i);
        const int c0 = __float_as_int(cv.x);
        const float4 x0 = __ldg(reinterpret_cast<const float4*>(x + ((size_t)c0 << 6) + c4));
        a0.x = fmaf(cv.y, x0.x, a0.x); a0.y = fmaf(cv.y, x0.y, a0.y);
        a0.z = fmaf(cv.y, x0.z, a0.z); a0.w = fmaf(cv.y, x0.w, a0.w);
    }

    float4 r;
    r.x = a0.x + a1.x; r.y = a0.y + a1.y; r.z = a0.z + a1.z; r.w = a0.w + a1.w;
    *reinterpret_cast<float4*>(out + ((size_t)row << 6) + c4) = r;
}

// ---------------------------------------------------------------------------
// GEMM via 3xTF32 mma.sync (R3-proven)
// ---------------------------------------------------------------------------
#define BM 128
#define BK 32

__device__ __forceinline__ void mma_tf32(float c[4],
                                         unsigned a0, unsigned a1, unsigned a2, unsigned a3,
                                         unsigned b0, unsigned b1)
{
    asm volatile(
        "mma.sync.aligned.m16n8k8.row.col.f32.tf32.tf32.f32 "
        "{%0,%1,%2,%3}, {%4,%5,%6,%7}, {%8,%9}, {%0,%1,%2,%3};"
        : "+f"(c[0]), "+f"(c[1]), "+f"(c[2]), "+f"(c[3])
        : "r"(a0), "r"(a1), "r"(a2), "r"(a3), "r"(b0), "r"(b1));
}

__global__ __launch_bounds__(256) void gemm_tf32_kernel(
    const float* __restrict__ A,
    const float* __restrict__ Bhi, const float* __restrict__ Blo,
    float* __restrict__ C, int n)
{
    __shared__ float As[BM][36];
    __shared__ float Bh[BK][72];
    __shared__ float Bl[BK][72];

    const int tid  = threadIdx.x;
    const int warp = tid >> 5;
    const int lane = tid & 31;
    const int g = lane >> 2;
    const int t = lane & 3;
    const int row0 = blockIdx.x * BM;

    const int am = tid >> 3;
    const int ak = (tid & 7) << 2;

    float c[8][4];
    #pragma unroll
    for (int j = 0; j < 8; j++)
        #pragma unroll
        for (int q = 0; q < 4; q++) c[j][q] = 0.f;

    for (int k0 = 0; k0 < DIN; k0 += BK) {
        #pragma unroll
        for (int p = 0; p < 4; p++) {
            int rl = am + p * 32;
            int r  = row0 + rl;
            float4 v = make_float4(0.f, 0.f, 0.f, 0.f);
            if (r < n)
                v = *reinterpret_cast<const float4*>(A + (size_t)r * DIN + k0 + ak);
            As[rl][ak + 0] = v.x; As[rl][ak + 1] = v.y;
            As[rl][ak + 2] = v.z; As[rl][ak + 3] = v.w;
        }
        #pragma unroll
        for (int q = 0; q < 2; q++) {
            int idx = tid * 2 + q;
            int bk = idx >> 4;
            int bn = (idx & 15) << 2;
            const float4 vh = *reinterpret_cast<const float4*>(Bhi + (size_t)(k0 + bk) * DOUT + bn);
            const float4 vl = *reinterpret_cast<const float4*>(Blo + (size_t)(k0 + bk) * DOUT + bn);
            Bh[bk][bn + 0] = vh.x; Bh[bk][bn + 1] = vh.y;
            Bh[bk][bn + 2] = vh.z; Bh[bk][bn + 3] = vh.w;
            Bl[bk][bn + 0] = vl.x; Bl[bk][bn + 1] = vl.y;
            Bl[bk][bn + 2] = vl.z; Bl[bk][bn + 3] = vl.w;
        }
        __syncthreads();

        #pragma unroll
        for (int kk = 0; kk < BK / 8; kk++) {
            const int kc = kk * 8;
            const float a0f = As[warp * 16 + g    ][kc + t    ];
            const float a1f = As[warp * 16 + g + 8][kc + t    ];
            const float a2f = As[warp * 16 + g    ][kc + t + 4];
            const float a3f = As[warp * 16 + g + 8][kc + t + 4];
            const unsigned ah0 = __float_as_uint(a0f) & 0xffffe000u;
            const unsigned ah1 = __float_as_uint(a1f) & 0xffffe000u;
            const unsigned ah2 = __float_as_uint(a2f) & 0xffffe000u;
            const unsigned ah3 = __float_as_uint(a3f) & 0xffffe000u;
            const unsigned al0 = __float_as_uint(a0f - __uint_as_float(ah0));
            const unsigned al1 = __float_as_uint(a1f - __uint_as_float(ah1));
            const unsigned al2 = __float_as_uint(a2f - __uint_as_float(ah2));
            const unsigned al3 = __float_as_uint(a3f - __uint_as_float(ah3));

            #pragma unroll
            for (int j = 0; j < 8; j++) {
                const unsigned bh0 = __float_as_uint(Bh[kc + t    ][j * 8 + g]);
                const unsigned bh1 = __float_as_uint(Bh[kc + t + 4][j * 8 + g]);
                const unsigned bl0 = __float_as_uint(Bl[kc + t    ][j * 8 + g]);
                const unsigned bl1 = __float_as_uint(Bl[kc + t + 4][j * 8 + g]);
                mma_tf32(c[j], ah0, ah1, ah2, ah3, bh0, bh1);
                mma_tf32(c[j], al0, al1, al2, al3, bh0, bh1);
                mma_tf32(c[j], ah0, ah1, ah2, ah3, bl0, bl1);
            }
        }
        __syncthreads();
    }

    const int rA = row0 + warp * 16 + g;
    const int rB = rA + 8;
    const bool okA = rA < n, okB = rB < n;
    #pragma unroll
    for (int j = 0; j < 8; j++) {
        const int col = j * 8 + 2 * t;
        if (okA) {
            float v0 = c[j][0]; v0 = (v0 > 0.f) ? v0 : NEG_SLOPE * v0;
            float v1 = c[j][1]; v1 = (v1 > 0.f) ? v1 : NEG_SLOPE * v1;
            C[(size_t)rA * DOUT + col]     = v0;
            C[(size_t)rA * DOUT + col + 1] = v1;
        }
        if (okB) {
            float v2 = c[j][2]; v2 = (v2 > 0.f) ? v2 : NEG_SLOPE * v2;
            float v3 = c[j][3]; v3 = (v3 > 0.f) ? v3 : NEG_SLOPE * v3;
            C[(size_t)rB * DOUT + col]     = v2;
            C[(size_t)rB * DOUT + col + 1] = v3;
        }
    }
}

// ---------------------------------------------------------------------------
extern "C" void kernel_launch(void* const* d_in, const int* in_sizes, int n_in,
                              void* d_out, int out_size)
{
    const float* features = (const float*)d_in[0];
    const float* weight   = (const float*)d_in[1];
    const int*   erows    = (const int*)d_in[2];
    const int*   ecols    = (const int*)d_in[3];
    const float* evals    = (const float*)d_in[4];
    float* out = (float*)d_out;

    const int n = in_sizes[0] / DIN;
    const int E = in_sizes[2];

    float* out_output = out;
    float* out_az     = out + (size_t)n * DOUT;

    float *support = nullptr, *bhi = nullptr, *blo = nullptr;
    int *rowptr = nullptr, *tmpoff = nullptr, *bsums = nullptr;
    float2* ecf = nullptr;
    cudaGetSymbolAddress((void**)&support, g_support);
    cudaGetSymbolAddress((void**)&bhi, g_Bhi);
    cudaGetSymbolAddress((void**)&blo, g_Blo);
    cudaGetSymbolAddress((void**)&rowptr, g_rowptr);
    cudaGetSymbolAddress((void**)&tmpoff, g_tmpoff);
    cudaGetSymbolAddress((void**)&bsums, g_bsums);
    cudaGetSymbolAddress((void**)&ecf, g_ecf);

    // ---- W split ----
    split_w_kernel<<<(DIN * DOUT + 255) / 256, 256>>>(weight, bhi, blo, DIN * DOUT);

    // ---- GEMM: support = leaky_relu(features @ W) ----
    gemm_tf32_kernel<<<(n + BM - 1) / BM, 256>>>(features, bhi, blo, support, n);

    // ---- CSR build ----
    cudaMemsetAsync(tmpoff, 0, (size_t)n * sizeof(int));          // reuse as counts
    hist_kernel<<<(E + 255) / 256, 256>>>(erows, tmpoff, E);
    const int nblocks = (n + SCAN_B - 1) / SCAN_B;                // 98
    scan_blocks_kernel<<<nblocks, SCAN_B>>>(tmpoff, rowptr, bsums, n);
    scan_sums_kernel<<<1, 128>>>(bsums, nblocks);
    add_offsets_kernel<<<(n + 255) / 256, 256>>>(rowptr, bsums, n, E);
    cudaMemcpyAsync(tmpoff, rowptr, (size_t)n * sizeof(int), cudaMemcpyDeviceToDevice);
    scatter_kernel<<<(E + 255) / 256, 256>>>(erows, ecols, evals, tmpoff, ecf, E);

    // ---- Phase 2: output = adj @ support (no atomics, writes every row) ----
    spmm_csr_kernel<<<(n + 15) / 16, 256>>>(rowptr, ecf, support, out_output, n);

    // ---- Phase 3: az = adj @ output ----
    spmm_csr_kernel<<<(n + 15) / 16, 256>>>(rowptr, ecf, out_output, out_az, n);
}

// round 6
// speedup vs baseline: 2.0751x; 1.2528x over previous
#include <cuda_runtime.h>
#include <cuda_bf16.h>
#include <cstdint>

#define DIN 512
#define DOUT 64
#define NEG_SLOPE 0.2f
#define N_MAX 100000
#define E_MAX 1600000

// ---------------- scratch (__device__ globals; no allocation allowed) ------
__device__ float    g_support[(size_t)N_MAX * DOUT];
__device__ unsigned g_Wp[32768];       // W as bf16 hi/lo, fragment-permuted

__device__ int    g_rowptr[N_MAX + 1];
__device__ int    g_tmpoff[N_MAX];
__device__ int    g_bsums[128];
__device__ float2 g_ecf[E_MAX];        // packed {col_bits, val}, row-sorted

// ---------------------------------------------------------------------------
// helpers
// ---------------------------------------------------------------------------
__device__ __forceinline__ unsigned pk(float lo, float hi) {
    unsigned r;
    asm("cvt.rn.bf16x2.f32 %0, %1, %2;" : "=r"(r) : "f"(hi), "f"(lo));
    return r;
}

__device__ __forceinline__ void mma_bf16(float c[4],
                                         unsigned a0, unsigned a1, unsigned a2, unsigned a3,
                                         unsigned b0, unsigned b1)
{
    asm volatile(
        "mma.sync.aligned.m16n8k16.row.col.f32.bf16.bf16.f32 "
        "{%0,%1,%2,%3}, {%4,%5,%6,%7}, {%8,%9}, {%0,%1,%2,%3};"
        : "+f"(c[0]), "+f"(c[1]), "+f"(c[2]), "+f"(c[3])
        : "r"(a0), "r"(a1), "r"(a2), "r"(a3), "r"(b0), "r"(b1));
}

// ---------------------------------------------------------------------------
// W pack: bf16 hi + bf16 residual lo, permuted to mma-fragment order.
// Consumption (per K-chunk of 32, kk in {0,1}, lane=(g<<2)|t):
//   bh0(j) = pack(W[16kk+2t][8j+g],  W[16kk+2t+1][8j+g])
//   bh1(j) = pack(W[16kk+2t+8][8j+g],W[16kk+2t+9][8j+g])
// stored as uint4 chunks: c=0..3 hi (bh0 j0-3, bh0 j4-7, bh1 j0-3, bh1 j4-7),
// c=4..7 same for lo.  linear = (((kc*2+kk)*8+c)*32+lane)*4+e
// ---------------------------------------------------------------------------
__global__ void pack_w_kernel(const float* __restrict__ W, unsigned* __restrict__ Wp)
{
    int i = blockIdx.x * blockDim.x + threadIdx.x;
    if (i >= (DIN / 2) * DOUT) return;
    int k2 = i >> 6, nn = i & 63;
    float w0 = W[(2 * k2) * DOUT + nn];
    float w1 = W[(2 * k2 + 1) * DOUT + nn];
    unsigned hv = pk(w0, w1);
    float r0 = w0 - __uint_as_float(hv << 16);
    float r1 = w1 - __uint_as_float(hv & 0xffff0000u);
    unsigned lv = pk(r0, r1);

    int kc = k2 >> 4, k2l = k2 & 15;
    int kk = k2l >> 3, t_ = k2l & 7, tt = t_ & 3, bs = t_ >> 2;
    int j = nn >> 3, gg = nn & 7, lane = gg * 4 + tt;
    int c = bs * 2 + (j >> 2), e = j & 3;
    int lin = (((kc * 2 + kk) * 8 + c) * 32 + lane) * 4 + e;
    Wp[lin] = hv;
    Wp[lin + 512] = lv;           // lo chunks sit 4 chunks (512 u32) later
}

// ---------------------------------------------------------------------------
// GEMM: C = leaky_relu(A @ W) via 3x bf16-split mma.sync.m16n8k16.
// BM=128, BK=32, 256 thr / 8 warps; warp owns 16 rows x 64 cols.
// Double-buffered dynamic smem; A converted fp32->bf16 hi/lo during STS.
// Stage layout (u32): Ah[128*20] | Al[128*20] | B[2048]; stride 7168 u32.
// ---------------------------------------------------------------------------
#define BM 128
#define GEMM_SMEM_BYTES (2 * 7168 * 4)

__global__ __launch_bounds__(256) void gemm_bf16x3_kernel(
    const float* __restrict__ A, const unsigned* __restrict__ Wp,
    float* __restrict__ C, int n)
{
    extern __shared__ unsigned sm[];
    const int tid  = threadIdx.x;
    const int warp = tid >> 5;
    const int lane = tid & 31;
    const int g = lane >> 2;
    const int t = lane & 3;
    const int row0 = blockIdx.x * BM;
    const int am = tid >> 3;          // 0..31
    const int ak = (tid & 7) << 2;    // 0..28
    const int p0 = ak >> 1;

    float acc[8][4];
    #pragma unroll
    for (int j = 0; j < 8; j++)
        #pragma unroll
        for (int q = 0; q < 4; q++) acc[j][q] = 0.f;

    float4 aR[4];
    uint4  bR[2];

    auto ldg = [&](int chunk) {
        const int k0 = chunk * 32;
        #pragma unroll
        for (int p = 0; p < 4; p++) {
            int r = row0 + am + p * 32;
            aR[p] = (r < n) ? *reinterpret_cast<const float4*>(A + (size_t)r * DIN + k0 + ak)
                            : make_float4(0.f, 0.f, 0.f, 0.f);
        }
        const uint4* gb = reinterpret_cast<const uint4*>(Wp + chunk * 2048 + tid * 8);
        bR[0] = gb[0];
        bR[1] = gb[1];
    };

    auto sts = [&](int buf) {
        unsigned* Ah = sm + buf * 7168;
        unsigned* Al = Ah + 2560;
        unsigned* Bb = Ah + 5120;
        #pragma unroll
        for (int p = 0; p < 4; p++) {
            int rl = am + p * 32;
            float4 v = aR[p];
            unsigned h01 = pk(v.x, v.y), h23 = pk(v.z, v.w);
            float r0 = v.x - __uint_as_float(h01 << 16);
            float r1 = v.y - __uint_as_float(h01 & 0xffff0000u);
            float r2 = v.z - __uint_as_float(h23 << 16);
            float r3 = v.w - __uint_as_float(h23 & 0xffff0000u);
            unsigned l01 = pk(r0, r1), l23 = pk(r2, r3);
            Ah[rl * 20 + p0]     = h01;
            Ah[rl * 20 + p0 + 1] = h23;
            Al[rl * 20 + p0]     = l01;
            Al[rl * 20 + p0 + 1] = l23;
        }
        uint4* sb = reinterpret_cast<uint4*>(Bb + tid * 8);
        sb[0] = bR[0];
        sb[1] = bR[1];
    };

    auto compute = [&](int buf) {
        const unsigned* Ah = sm + buf * 7168;
        const unsigned* Al = Ah + 2560;
        const unsigned* Bb = Ah + 5120;
        #pragma unroll
        for (int kk = 0; kk < 2; kk++) {
            const int rb = (warp * 16 + g) * 20 + kk * 8 + t;
            const unsigned ah0 = Ah[rb],       ah1 = Ah[rb + 160];
            const unsigned ah2 = Ah[rb + 4],   ah3 = Ah[rb + 164];
            const unsigned al0 = Al[rb],       al1 = Al[rb + 160];
            const unsigned al2 = Al[rb + 4],   al3 = Al[rb + 164];
            uint4 q[8];
            #pragma unroll
            for (int c = 0; c < 8; c++)
                q[c] = *reinterpret_cast<const uint4*>(Bb + kk * 1024 + (c * 32 + lane) * 4);
            #pragma unroll
            for (int j = 0; j < 8; j++) {
                const uint4 h0 = q[(j >> 2)];
                const uint4 h1 = q[2 + (j >> 2)];
                const uint4 l0 = q[4 + (j >> 2)];
                const uint4 l1 = q[6 + (j >> 2)];
                const int e = j & 3;
                const unsigned b0h = (e == 0) ? h0.x : (e == 1) ? h0.y : (e == 2) ? h0.z : h0.w;
                const unsigned b1h = (e == 0) ? h1.x : (e == 1) ? h1.y : (e == 2) ? h1.z : h1.w;
                const unsigned b0l = (e == 0) ? l0.x : (e == 1) ? l0.y : (e == 2) ? l0.z : l0.w;
                const unsigned b1l = (e == 0) ? l1.x : (e == 1) ? l1.y : (e == 2) ? l1.z : l1.w;
                mma_bf16(acc[j], ah0, ah1, ah2, ah3, b0h, b1h);   // Ah*Bh
                mma_bf16(acc[j], al0, al1, al2, al3, b0h, b1h);   // Al*Bh
                mma_bf16(acc[j], ah0, ah1, ah2, ah3, b0l, b1l);   // Ah*Bl
            }
        }
    };

    // pipeline: prefetch chunk 0, then overlap ldg(i+1) with compute(i)
    ldg(0);
    sts(0);
    __syncthreads();
    #pragma unroll 1
    for (int i = 0; i < 16; i++) {
        const int cur = i & 1;
        if (i + 1 < 16) ldg(i + 1);
        compute(cur);
        if (i + 1 < 16) sts(1 - cur);
        __syncthreads();
    }

    // epilogue: LeakyReLU + store (c0=(g,2t), c1=(g,2t+1), c2=(g+8,2t), c3=(g+8,2t+1))
    const int rA = row0 + warp * 16 + g;
    const int rB = rA + 8;
    const bool okA = rA < n, okB = rB < n;
    #pragma unroll
    for (int j = 0; j < 8; j++) {
        const int col = j * 8 + 2 * t;
        if (okA) {
            float v0 = acc[j][0]; v0 = (v0 > 0.f) ? v0 : NEG_SLOPE * v0;
            float v1 = acc[j][1]; v1 = (v1 > 0.f) ? v1 : NEG_SLOPE * v1;
            C[(size_t)rA * DOUT + col]     = v0;
            C[(size_t)rA * DOUT + col + 1] = v1;
        }
        if (okB) {
            float v2 = acc[j][2]; v2 = (v2 > 0.f) ? v2 : NEG_SLOPE * v2;
            float v3 = acc[j][3]; v3 = (v3 > 0.f) ? v3 : NEG_SLOPE * v3;
            C[(size_t)rB * DOUT + col]     = v2;
            C[(size_t)rB * DOUT + col + 1] = v3;
        }
    }
}

// ---------------------------------------------------------------------------
// CSR build: histogram -> 2-level exclusive scan -> scatter permute (R5-proven)
// ---------------------------------------------------------------------------
__global__ void hist_kernel(const int* __restrict__ rows, int* __restrict__ cnt, int E)
{
    int i = blockIdx.x * blockDim.x + threadIdx.x;
    if (i < E) atomicAdd(cnt + rows[i], 1);
}

#define SCAN_B 1024
__global__ __launch_bounds__(SCAN_B) void scan_blocks_kernel(
    const int* __restrict__ cnt, int* __restrict__ rowptr,
    int* __restrict__ bsums, int n)
{
    __shared__ int s[SCAN_B];
    const int tid = threadIdx.x;
    const int i = blockIdx.x * SCAN_B + tid;
    int v = (i < n) ? cnt[i] : 0;
    s[tid] = v;
    __syncthreads();
    #pragma unroll
    for (int off = 1; off < SCAN_B; off <<= 1) {
        int t = (tid >= off) ? s[tid - off] : 0;
        __syncthreads();
        s[tid] += t;
        __syncthreads();
    }
    if (i < n) rowptr[i] = s[tid] - v;
    if (tid == SCAN_B - 1) bsums[blockIdx.x] = s[tid];
}

__global__ __launch_bounds__(128) void scan_sums_kernel(int* __restrict__ bsums, int nb)
{
    __shared__ int s[128];
    const int tid = threadIdx.x;
    int v = (tid < nb) ? bsums[tid] : 0;
    s[tid] = v;
    __syncthreads();
    #pragma unroll
    for (int off = 1; off < 128; off <<= 1) {
        int t = (tid >= off) ? s[tid - off] : 0;
        __syncthreads();
        s[tid] += t;
        __syncthreads();
    }
    if (tid < nb) bsums[tid] = s[tid] - v;
}

__global__ void add_offsets_kernel(int* __restrict__ rowptr,
                                   const int* __restrict__ bsums, int n, int E)
{
    int i = blockIdx.x * blockDim.x + threadIdx.x;
    if (i < n) rowptr[i] += bsums[i >> 10];
    if (i == 0) rowptr[n] = E;
}

__global__ void scatter_kernel(const int* __restrict__ rows,
                               const int* __restrict__ cols,
                               const float* __restrict__ vals,
                               int* __restrict__ off,
                               float2* __restrict__ ecf, int E)
{
    int i = blockIdx.x * blockDim.x + threadIdx.x;
    if (i < E) {
        int r = rows[i];
        int p = atomicAdd(off + r, 1);
        ecf[p] = make_float2(__int_as_float(cols[i]), vals[i]);
    }
}

// ---------------------------------------------------------------------------
// CSR SpMM (R5-proven): 16 threads/row, float4/thread, zero atomics.
// ---------------------------------------------------------------------------
__global__ __launch_bounds__(256) void spmm_csr_kernel(
    const int* __restrict__ rowptr, const float2* __restrict__ ecf,
    const float* __restrict__ x, float* __restrict__ out, int n)
{
    const int tid = threadIdx.x;
    const int row = blockIdx.x * 16 + (tid >> 4);
    const int c4 = (tid & 15) << 2;
    if (row >= n) return;

    const int s = __ldg(rowptr + row);
    const int e = __ldg(rowptr + row + 1);

    float4 a0 = make_float4(0.f, 0.f, 0.f, 0.f);
    float4 a1 = make_float4(0.f, 0.f, 0.f, 0.f);

    int i = s;
    for (; i + 2 <= e; i += 2) {
        const float2 cv0 = __ldg(ecf + i);
        const float2 cv1 = __ldg(ecf + i + 1);
        const int c0 = __float_as_int(cv0.x);
        const int c1 = __float_as_int(cv1.x);
        const float4 x0 = __ldg(reinterpret_cast<const float4*>(x + ((size_t)c0 << 6) + c4));
        const float4 x1 = __ldg(reinterpret_cast<const float4*>(x + ((size_t)c1 << 6) + c4));
        a0.x = fmaf(cv0.y, x0.x, a0.x); a0.y = fmaf(cv0.y, x0.y, a0.y);
        a0.z = fmaf(cv0.y, x0.z, a0.z); a0.w = fmaf(cv0.y, x0.w, a0.w);
        a1.x = fmaf(cv1.y, x1.x, a1.x); a1.y = fmaf(cv1.y, x1.y, a1.y);
        a1.z = fmaf(cv1.y, x1.z, a1.z); a1.w = fmaf(cv1.y, x1.w, a1.w);
    }
    if (i < e) {
        const float2 cv = __ldg(ecf + i);
        const int c0 = __float_as_int(cv.x);
        const float4 x0 = __ldg(reinterpret_cast<const float4*>(x + ((size_t)c0 << 6) + c4));
        a0.x = fmaf(cv.y, x0.x, a0.x); a0.y = fmaf(cv.y, x0.y, a0.y);
        a0.z = fmaf(cv.y, x0.z, a0.z); a0.w = fmaf(cv.y, x0.w, a0.w);
    }

    float4 r;
    r.x = a0.x + a1.x; r.y = a0.y + a1.y; r.z = a0.z + a1.z; r.w = a0.w + a1.w;
    *reinterpret_cast<float4*>(out + ((size_t)row << 6) + c4) = r;
}

// ---------------------------------------------------------------------------
extern "C" void kernel_launch(void* const* d_in, const int* in_sizes, int n_in,
                              void* d_out, int out_size)
{
    const float* features = (const float*)d_in[0];
    const float* weight   = (const float*)d_in[1];
    const int*   erows    = (const int*)d_in[2];
    const int*   ecols    = (const int*)d_in[3];
    const float* evals    = (const float*)d_in[4];
    float* out = (float*)d_out;

    const int n = in_sizes[0] / DIN;
    const int E = in_sizes[2];

    float* out_output = out;
    float* out_az     = out + (size_t)n * DOUT;

    float*    support = nullptr;
    unsigned* wp = nullptr;
    int *rowptr = nullptr, *tmpoff = nullptr, *bsums = nullptr;
    float2* ecf = nullptr;
    cudaGetSymbolAddress((void**)&support, g_support);
    cudaGetSymbolAddress((void**)&wp, g_Wp);
    cudaGetSymbolAddress((void**)&rowptr, g_rowptr);
    cudaGetSymbolAddress((void**)&tmpoff, g_tmpoff);
    cudaGetSymbolAddress((void**)&bsums, g_bsums);
    cudaGetSymbolAddress((void**)&ecf, g_ecf);

    // ---- W pack (bf16 hi/lo, fragment-permuted) ----
    pack_w_kernel<<<((DIN / 2) * DOUT + 255) / 256, 256>>>(weight, wp);

    // ---- GEMM: support = leaky_relu(features @ W) ----
    cudaFuncSetAttribute(gemm_bf16x3_kernel,
                         cudaFuncAttributeMaxDynamicSharedMemorySize, GEMM_SMEM_BYTES);
    gemm_bf16x3_kernel<<<(n + BM - 1) / BM, 256, GEMM_SMEM_BYTES>>>(features, wp, support, n);

    // ---- CSR build ----
    cudaMemsetAsync(tmpoff, 0, (size_t)n * sizeof(int));
    hist_kernel<<<(E + 255) / 256, 256>>>(erows, tmpoff, E);
    const int nblocks = (n + SCAN_B - 1) / SCAN_B;
    scan_blocks_kernel<<<nblocks, SCAN_B>>>(tmpoff, rowptr, bsums, n);
    scan_sums_kernel<<<1, 128>>>(bsums, nblocks);
    add_offsets_kernel<<<(n + 255) / 256, 256>>>(rowptr, bsums, n, E);
    cudaMemcpyAsync(tmpoff, rowptr, (size_t)n * sizeof(int), cudaMemcpyDeviceToDevice);
    scatter_kernel<<<(E + 255) / 256, 256>>>(erows, ecols, evals, tmpoff, ecf, E);

    // ---- Phase 2: output = adj @ support ----
    spmm_csr_kernel<<<(n + 15) / 16, 256>>>(rowptr, ecf, support, out_output, n);

    // ---- Phase 3: az = adj @ output ----
    spmm_csr_kernel<<<(n + 15) / 16, 256>>>(rowptr, ecf, out_output, out_az, n);
}